// round 4
// baseline (speedup 1.0000x reference)
#include <cuda_runtime.h>
#include <cstdint>

#define N_NODES 50000
#define N_EDGES 800000
#define SCAN_BLOCKS ((N_NODES + 255) / 256)   // 196
#define NTILES ((N_NODES + 31) / 32)          // 1563
#define GEMM_GRID 148

// ---- scratch (device globals; no allocs) ----
__device__ __align__(16) float4 g_neigh4[N_NODES * 32];   // mean-aggregated neigh
__device__ int g_deg_i[N_NODES];     // in-degree counts
__device__ int g_cursor[N_NODES];    // exclusive offsets -> cursors after binfill
__device__ int g_src_bin[N_EDGES];   // src ids sorted by dst
__device__ int g_scan_val[SCAN_BLOCKS];
__device__ volatile int g_scan_flag[SCAN_BLOCKS];
__device__ int g_ei_is64;            // edge_index dtype flag

// ---- helpers: dtype-agnostic edge index reads ----
__device__ __forceinline__ int load_src(const long long* ei, int e) {
    return g_ei_is64 ? (int)__ldg(ei + e) : __ldg(((const int*)ei) + e);
}
__device__ __forceinline__ int load_dst(const long long* ei, int e) {
    return g_ei_is64 ? (int)__ldg(ei + N_EDGES + e) : __ldg(((const int*)ei) + N_EDGES + e);
}

// ---------------------------------------------------------------------------
// K1: zero degree counters + scan state + probe edge_index dtype
// ---------------------------------------------------------------------------
__global__ void __launch_bounds__(256) k_zero(const long long* __restrict__ ei) {
    int i = blockIdx.x * blockDim.x + threadIdx.x;
    if (i < N_NODES) g_deg_i[i] = 0;
    if (i < SCAN_BLOCKS) g_scan_flag[i] = 0;
    if (i == 0) {
        int ok = 1;
        for (int k = 0; k < 64; k++) {
            long long v = ei[k];
            if (v < 0 || v >= N_NODES) { ok = 0; break; }
        }
        g_ei_is64 = ok;
    }
}

// ---------------------------------------------------------------------------
// K2: in-degree histogram
// ---------------------------------------------------------------------------
__global__ void __launch_bounds__(256) k_hist(const long long* __restrict__ ei) {
    int e = blockIdx.x * blockDim.x + threadIdx.x;
    if (e >= N_EDGES) return;
    int d = load_dst(ei, e);
    if ((unsigned)d < N_NODES) atomicAdd(&g_deg_i[d], 1);
}

// ---------------------------------------------------------------------------
// K3: single-pass exclusive scan of degrees -> g_cursor.
// Per-block inclusive scan, publish block aggregate (fence + flag), then
// full lookback: sum aggregates of all predecessor blocks. Flags are
// re-zeroed by k_zero each replay, so this is graph-replay safe.
// ---------------------------------------------------------------------------
__global__ void __launch_bounds__(256) k_scan() {
    __shared__ int s[256];
    __shared__ int carry;
    const int b = blockIdx.x;
    const int tid = threadIdx.x;
    const int i = b * 256 + tid;

    int v = (i < N_NODES) ? g_deg_i[i] : 0;
    s[tid] = v;
    __syncthreads();
    int acc = v;
    #pragma unroll
    for (int off = 1; off < 256; off <<= 1) {
        int t = (tid >= off) ? s[tid - off] : 0;
        __syncthreads();
        acc += t;
        s[tid] = acc;
        __syncthreads();
    }
    if (tid == 255) {
        g_scan_val[b] = acc;          // block aggregate
        __threadfence();
        g_scan_flag[b] = 1;
    }
    if (tid == 0) carry = 0;
    __syncthreads();

    // lookback: sum all predecessor aggregates (published fast, in parallel)
    int sum = 0;
    for (int p = tid; p < b; p += 256) {
        while (g_scan_flag[p] == 0) { }   // spin; predecessors are resident first
        sum += g_scan_val[p];
    }
    if (sum) atomicAdd(&carry, sum);
    __syncthreads();

    if (i < N_NODES) g_cursor[i] = carry + (acc - v);   // exclusive prefix
}

// ---------------------------------------------------------------------------
// K4: bin fill — counting-sort src ids by dst
// ---------------------------------------------------------------------------
__global__ void __launch_bounds__(256) k_binfill(const long long* __restrict__ ei) {
    int e = blockIdx.x * blockDim.x + threadIdx.x;
    if (e >= N_EDGES) return;
    int s = load_src(ei, e);
    int d = load_dst(ei, e);
    if ((unsigned)s >= N_NODES || (unsigned)d >= N_NODES) return;
    int pos = atomicAdd(&g_cursor[d], 1);
    g_src_bin[pos] = s;
}

// ---------------------------------------------------------------------------
// K5: gather-aggregate. One warp per node; lane = float4 channel chunk
// (coalesced 512B per warp-load). Registers accumulate; one clean write.
// ---------------------------------------------------------------------------
__global__ void __launch_bounds__(256) k_aggregate(const float4* __restrict__ x4) {
    int n = (blockIdx.x * blockDim.x + threadIdx.x) >> 5;
    int lane = threadIdx.x & 31;
    if (n >= N_NODES) return;

    int end = g_cursor[n];          // == off[n] + deg[n] after binfill
    int deg = g_deg_i[n];
    int beg = end - deg;

    float4 a0 = make_float4(0.f, 0.f, 0.f, 0.f);
    float4 a1 = make_float4(0.f, 0.f, 0.f, 0.f);

    for (int base = beg; base < end; base += 32) {
        int m = min(32, end - base);
        int s = (base + lane < end) ? __ldg(g_src_bin + base + lane) : 0;
        int j = 0;
        for (; j + 1 < m; j += 2) {
            int s0 = __shfl_sync(0xffffffffu, s, j);
            int s1 = __shfl_sync(0xffffffffu, s, j + 1);
            float4 v0 = __ldg(x4 + s0 * 32 + lane);
            float4 v1 = __ldg(x4 + s1 * 32 + lane);
            a0.x += v0.x; a0.y += v0.y; a0.z += v0.z; a0.w += v0.w;
            a1.x += v1.x; a1.y += v1.y; a1.z += v1.z; a1.w += v1.w;
        }
        if (j < m) {
            int s0 = __shfl_sync(0xffffffffu, s, j);
            float4 v0 = __ldg(x4 + s0 * 32 + lane);
            a0.x += v0.x; a0.y += v0.y; a0.z += v0.z; a0.w += v0.w;
        }
    }
    float sc = 1.0f / fmaxf((float)deg, 1.0f);
    g_neigh4[n * 32 + lane] = make_float4((a0.x + a1.x) * sc, (a0.y + a1.y) * sc,
                                          (a0.z + a1.z) * sc, (a0.w + a1.w) * sc);
}

// ---------------------------------------------------------------------------
// K6: PERSISTENT fused [x | neigh] @ W^T + b, row L2-normalize.
// Grid = 148 blocks; W (128 KB, XOR-swizzled) staged into smem ONCE per
// block, then grid-stride loop over 32-row tiles staging only h (33 KB).
// ---------------------------------------------------------------------------
#define FMA2(acc, av, wv) \
    asm("fma.rn.f32x2 %0, %1, %2, %0;" : "+l"(acc) : "l"(av), "l"(wv))
#define UNPACK2(lo, hi, v) \
    asm("mov.b64 {%0,%1}, %2;" : "=f"(lo), "=f"(hi) : "l"(v))

__global__ void __launch_bounds__(256, 1) gemm_norm_kernel(
    const float4* __restrict__ x4,
    const float4* __restrict__ W4,     // [128][64] float4 (W[c][k])
    const float*  __restrict__ bias,   // [128]
    float4*       __restrict__ out4)   // [N_NODES][32]
{
    extern __shared__ float4 sm[];
    float4* Ws = sm;            // 8192 float4 = 128 KB, XOR-swizzled
    float4* hs = sm + 8192;     // [32 rows][65] padded = 33.3 KB

    const int tid = threadIdx.x;
    const int cg  = tid & 7;
    const int rw  = tid >> 3;

    // Stage W once: Ws[(c<<6) | (chunk ^ (c>>4))] = W[c][chunk]
    #pragma unroll
    for (int i = tid; i < 8192; i += 256) {
        int c = i >> 6, ch = i & 63;
        Ws[(c << 6) | (ch ^ (c >> 4))] = __ldg(W4 + i);
    }

    const ulonglong2* WsU = (const ulonglong2*)Ws;
    const ulonglong2* hsU = (const ulonglong2*)hs;

    for (int tile = blockIdx.x; tile < NTILES; tile += GEMM_GRID) {
        const int base = tile * 32;

        // Stage h = [x | neigh] for 32 rows
        #pragma unroll
        for (int i = tid; i < 2048; i += 256) {
            int r = i >> 6, k4 = i & 63;
            int row = base + r;
            float4 v = make_float4(0.f, 0.f, 0.f, 0.f);
            if (row < N_NODES)
                v = (k4 < 32) ? __ldg(x4 + row * 32 + k4)
                              : g_neigh4[row * 32 + (k4 - 32)];
            hs[r * 65 + k4] = v;
        }
        __syncthreads();

        unsigned long long accA[16], accB[16];
        #pragma unroll
        for (int j = 0; j < 16; j++) { accA[j] = 0ull; accB[j] = 0ull; }

        #pragma unroll 4
        for (int k4 = 0; k4 < 64; ++k4) {
            ulonglong2 a = hsU[rw * 65 + k4];
            int wbase = (cg << 10) | (k4 ^ cg);
            #pragma unroll
            for (int j = 0; j < 16; j++) {
                ulonglong2 w = WsU[wbase + (j << 6)];
                FMA2(accA[j], a.x, w.x);
                FMA2(accB[j], a.y, w.y);
            }
        }

        float o[16];
        float ss = 0.f;
        #pragma unroll
        for (int j = 0; j < 16; j++) {
            float x0, x1, y0, y1;
            UNPACK2(x0, x1, accA[j]);
            UNPACK2(y0, y1, accB[j]);
            float v = (x0 + x1) + (y0 + y1) + __ldg(bias + cg * 16 + j);
            o[j] = v;
            ss += v * v;
        }
        ss += __shfl_xor_sync(0xffffffffu, ss, 1);
        ss += __shfl_xor_sync(0xffffffffu, ss, 2);
        ss += __shfl_xor_sync(0xffffffffu, ss, 4);
        float sc = 1.0f / fmaxf(sqrtf(ss), 1e-12f);

        int row = base + rw;
        if (row < N_NODES) {
            #pragma unroll
            for (int q = 0; q < 4; q++) {
                out4[row * 32 + cg * 4 + q] =
                    make_float4(o[4*q] * sc, o[4*q+1] * sc, o[4*q+2] * sc, o[4*q+3] * sc);
            }
        }
        __syncthreads();   // hs reused next tile
    }
}

// ---------------------------------------------------------------------------
extern "C" void kernel_launch(void* const* d_in, const int* in_sizes, int n_in,
                              void* d_out, int out_size) {
    const float4*    x4   = (const float4*)d_in[0];
    const long long* ei   = (const long long*)d_in[1];
    const float4*    W4   = (const float4*)d_in[2];
    const float*     bias = (const float*)d_in[3];
    float4*          out4 = (float4*)d_out;

    const int smem_bytes = (8192 + 32 * 65) * 16;  // 164352
    cudaFuncSetAttribute(gemm_norm_kernel,
                         cudaFuncAttributeMaxDynamicSharedMemorySize, smem_bytes);

    const int EB = (N_EDGES + 255) / 256;   // 3125

    k_zero<<<SCAN_BLOCKS, 256>>>(ei);
    k_hist<<<EB, 256>>>(ei);
    k_scan<<<SCAN_BLOCKS, 256>>>();
    k_binfill<<<EB, 256>>>(ei);
    k_aggregate<<<(N_NODES * 32 + 255) / 256, 256>>>(x4);
    gemm_norm_kernel<<<GEMM_GRID, 256, smem_bytes>>>(x4, W4, bias, out4);
}

// round 5
// speedup vs baseline: 1.6006x; 1.6006x over previous
#include <cuda_runtime.h>
#include <cstdint>

#define N_NODES 50000
#define N_EDGES 800000
#define SCAN_BLOCKS ((N_NODES + 255) / 256)   // 196
#define GEMM_ROWS 64
#define NTILES ((N_NODES + GEMM_ROWS - 1) / GEMM_ROWS)   // 782
#define GEMM_GRID 148

// ---- scratch (device globals; no allocs) ----
__device__ __align__(16) float4 g_neigh4[N_NODES * 32];   // mean-aggregated neigh
__device__ int g_deg_i[N_NODES];     // in-degree counts
__device__ int g_cursor[N_NODES];    // exclusive offsets -> cursors after binfill
__device__ int g_src_bin[N_EDGES];   // src ids sorted by dst
__device__ int g_scan_val[SCAN_BLOCKS];
__device__ volatile int g_scan_flag[SCAN_BLOCKS];
__device__ int g_ei_is64;            // edge_index dtype flag

// ---- helpers: dtype-agnostic edge index reads ----
__device__ __forceinline__ int load_src(const long long* ei, int e) {
    return g_ei_is64 ? (int)__ldg(ei + e) : __ldg(((const int*)ei) + e);
}
__device__ __forceinline__ int load_dst(const long long* ei, int e) {
    return g_ei_is64 ? (int)__ldg(ei + N_EDGES + e) : __ldg(((const int*)ei) + N_EDGES + e);
}

// ---------------------------------------------------------------------------
// K1: zero degree counters + scan state + probe edge_index dtype
// ---------------------------------------------------------------------------
__global__ void __launch_bounds__(256) k_zero(const long long* __restrict__ ei) {
    int i = blockIdx.x * blockDim.x + threadIdx.x;
    if (i < N_NODES) g_deg_i[i] = 0;
    if (i < SCAN_BLOCKS) g_scan_flag[i] = 0;
    if (i == 0) {
        int ok = 1;
        for (int k = 0; k < 64; k++) {
            long long v = ei[k];
            if (v < 0 || v >= N_NODES) { ok = 0; break; }
        }
        g_ei_is64 = ok;
    }
}

// ---------------------------------------------------------------------------
// K2: in-degree histogram
// ---------------------------------------------------------------------------
__global__ void __launch_bounds__(256) k_hist(const long long* __restrict__ ei) {
    int e = blockIdx.x * blockDim.x + threadIdx.x;
    if (e >= N_EDGES) return;
    int d = load_dst(ei, e);
    if ((unsigned)d < N_NODES) atomicAdd(&g_deg_i[d], 1);
}

// ---------------------------------------------------------------------------
// K3: single-pass exclusive scan of degrees -> g_cursor (full lookback).
// Flags re-zeroed by k_zero each replay -> graph-replay safe.
// ---------------------------------------------------------------------------
__global__ void __launch_bounds__(256) k_scan() {
    __shared__ int s[256];
    __shared__ int carry;
    const int b = blockIdx.x;
    const int tid = threadIdx.x;
    const int i = b * 256 + tid;

    int v = (i < N_NODES) ? g_deg_i[i] : 0;
    s[tid] = v;
    __syncthreads();
    int acc = v;
    #pragma unroll
    for (int off = 1; off < 256; off <<= 1) {
        int t = (tid >= off) ? s[tid - off] : 0;
        __syncthreads();
        acc += t;
        s[tid] = acc;
        __syncthreads();
    }
    if (tid == 255) {
        g_scan_val[b] = acc;
        __threadfence();
        g_scan_flag[b] = 1;
    }
    if (tid == 0) carry = 0;
    __syncthreads();

    int sum = 0;
    for (int p = tid; p < b; p += 256) {
        while (g_scan_flag[p] == 0) { }
        sum += g_scan_val[p];
    }
    if (sum) atomicAdd(&carry, sum);
    __syncthreads();

    if (i < N_NODES) g_cursor[i] = carry + (acc - v);
}

// ---------------------------------------------------------------------------
// K4: bin fill — counting-sort src ids by dst
// ---------------------------------------------------------------------------
__global__ void __launch_bounds__(256) k_binfill(const long long* __restrict__ ei) {
    int e = blockIdx.x * blockDim.x + threadIdx.x;
    if (e >= N_EDGES) return;
    int s = load_src(ei, e);
    int d = load_dst(ei, e);
    if ((unsigned)s >= N_NODES || (unsigned)d >= N_NODES) return;
    int pos = atomicAdd(&g_cursor[d], 1);
    g_src_bin[pos] = s;
}

// ---------------------------------------------------------------------------
// K5: gather-aggregate. One warp per node; lane = float4 channel chunk.
// ---------------------------------------------------------------------------
__global__ void __launch_bounds__(256) k_aggregate(const float4* __restrict__ x4) {
    int n = (blockIdx.x * blockDim.x + threadIdx.x) >> 5;
    int lane = threadIdx.x & 31;
    if (n >= N_NODES) return;

    int end = g_cursor[n];
    int deg = g_deg_i[n];
    int beg = end - deg;

    float4 a0 = make_float4(0.f, 0.f, 0.f, 0.f);
    float4 a1 = make_float4(0.f, 0.f, 0.f, 0.f);

    for (int base = beg; base < end; base += 32) {
        int m = min(32, end - base);
        int s = (base + lane < end) ? __ldg(g_src_bin + base + lane) : 0;
        int j = 0;
        for (; j + 1 < m; j += 2) {
            int s0 = __shfl_sync(0xffffffffu, s, j);
            int s1 = __shfl_sync(0xffffffffu, s, j + 1);
            float4 v0 = __ldg(x4 + s0 * 32 + lane);
            float4 v1 = __ldg(x4 + s1 * 32 + lane);
            a0.x += v0.x; a0.y += v0.y; a0.z += v0.z; a0.w += v0.w;
            a1.x += v1.x; a1.y += v1.y; a1.z += v1.z; a1.w += v1.w;
        }
        if (j < m) {
            int s0 = __shfl_sync(0xffffffffu, s, j);
            float4 v0 = __ldg(x4 + s0 * 32 + lane);
            a0.x += v0.x; a0.y += v0.y; a0.z += v0.z; a0.w += v0.w;
        }
    }
    float sc = 1.0f / fmaxf((float)deg, 1.0f);
    g_neigh4[n * 32 + lane] = make_float4((a0.x + a1.x) * sc, (a0.y + a1.y) * sc,
                                          (a0.z + a1.z) * sc, (a0.w + a1.w) * sc);
}

// ---------------------------------------------------------------------------
// K6: PERSISTENT register-blocked GEMM + bias + row L2-normalize.
// Tile: 64 rows x 128 cols per block iteration, 256 threads.
// Thread (cg = tid&15, rg = tid>>4) computes rows rg*4..+3, cols cg*8..+7.
// Per k4: 4 a-loads (broadcast, 1cyc) + 8 w-loads (16 distinct cols,
// k4^(c>>3) swizzle -> 2cyc floor) feed 64 FMA2 -> FMA-bound (160 vs 256).
// ---------------------------------------------------------------------------
#define FMA2(acc, av, wv) \
    asm("fma.rn.f32x2 %0, %1, %2, %0;" : "+l"(acc) : "l"(av), "l"(wv))
#define UNPACK2(lo, hi, v) \
    asm("mov.b64 {%0,%1}, %2;" : "=f"(lo), "=f"(hi) : "l"(v))

__global__ void __launch_bounds__(256, 1) gemm_norm_kernel(
    const float4* __restrict__ x4,
    const float4* __restrict__ W4,     // [128][64] float4 (W[c][k])
    const float*  __restrict__ bias,   // [128]
    float4*       __restrict__ out4)   // [N_NODES][32]
{
    extern __shared__ float4 sm[];
    float4* Ws = sm;                 // 8192 float4 = 128 KB, swizzled
    float4* hs = sm + 8192;          // [64 rows][65 float4] = 66560 B

    const int tid = threadIdx.x;
    const int cg  = tid & 15;        // col group: cols cg*8 .. cg*8+7
    const int rg  = tid >> 4;        // row group: rows rg*4 .. rg*4+3

    // Stage W once: Ws[(c<<6) | (ch ^ (c>>3))] = W[c][ch]
    #pragma unroll
    for (int i = tid; i < 8192; i += 256) {
        int c = i >> 6, ch = i & 63;
        Ws[(c << 6) | (ch ^ (c >> 3))] = __ldg(W4 + i);
    }

    // Hoist bias for this thread's 8 columns
    float bb[8];
    #pragma unroll
    for (int j = 0; j < 8; j++) bb[j] = __ldg(bias + cg * 8 + j);

    const ulonglong2* WsU = (const ulonglong2*)Ws;
    const ulonglong2* hsU = (const ulonglong2*)hs;

    for (int tile = blockIdx.x; tile < NTILES; tile += GEMM_GRID) {
        const int base = tile * GEMM_ROWS;

        // Stage h = [x | neigh] for 64 rows (neigh already mean-scaled)
        #pragma unroll
        for (int i = tid; i < 64 * 64; i += 256) {
            int r = i >> 6, k4 = i & 63;
            int row = base + r;
            float4 v = make_float4(0.f, 0.f, 0.f, 0.f);
            if (row < N_NODES)
                v = (k4 < 32) ? __ldg(x4 + row * 32 + k4)
                              : g_neigh4[row * 32 + (k4 - 32)];
            hs[r * 65 + k4] = v;
        }
        __syncthreads();

        // acc[r][j]: one u64 (f32x2 partial pair) per output element
        unsigned long long acc[4][8];
        #pragma unroll
        for (int r = 0; r < 4; r++)
            #pragma unroll
            for (int j = 0; j < 8; j++) acc[r][j] = 0ull;

        #pragma unroll 2
        for (int k4 = 0; k4 < 64; ++k4) {
            ulonglong2 a0 = hsU[(rg * 4 + 0) * 65 + k4];
            ulonglong2 a1 = hsU[(rg * 4 + 1) * 65 + k4];
            ulonglong2 a2 = hsU[(rg * 4 + 2) * 65 + k4];
            ulonglong2 a3 = hsU[(rg * 4 + 3) * 65 + k4];
            const int sw = k4 ^ cg;                 // c>>3 == cg for all 8 cols
            #pragma unroll
            for (int j = 0; j < 8; j++) {
                ulonglong2 w = WsU[(((cg << 3) | j) << 6) | sw];
                FMA2(acc[0][j], a0.x, w.x);
                FMA2(acc[0][j], a0.y, w.y);
                FMA2(acc[1][j], a1.x, w.x);
                FMA2(acc[1][j], a1.y, w.y);
                FMA2(acc[2][j], a2.x, w.x);
                FMA2(acc[2][j], a2.y, w.y);
                FMA2(acc[3][j], a3.x, w.x);
                FMA2(acc[3][j], a3.y, w.y);
            }
        }

        // Epilogue: per row r — bias, squared-sum reduce across 16 cgs, norm
        #pragma unroll
        for (int r = 0; r < 4; r++) {
            float o[8];
            float ss = 0.f;
            #pragma unroll
            for (int j = 0; j < 8; j++) {
                float lo, hi;
                UNPACK2(lo, hi, acc[r][j]);
                float v = lo + hi + bb[j];
                o[j] = v;
                ss += v * v;
            }
            // cg lanes are bits 0..3 of the lane id
            ss += __shfl_xor_sync(0xffffffffu, ss, 1);
            ss += __shfl_xor_sync(0xffffffffu, ss, 2);
            ss += __shfl_xor_sync(0xffffffffu, ss, 4);
            ss += __shfl_xor_sync(0xffffffffu, ss, 8);
            float sc = 1.0f / fmaxf(sqrtf(ss), 1e-12f);

            int row = base + rg * 4 + r;
            if (row < N_NODES) {
                out4[row * 32 + cg * 2 + 0] =
                    make_float4(o[0] * sc, o[1] * sc, o[2] * sc, o[3] * sc);
                out4[row * 32 + cg * 2 + 1] =
                    make_float4(o[4] * sc, o[5] * sc, o[6] * sc, o[7] * sc);
            }
        }
        __syncthreads();   // hs reused next tile
    }
}

// ---------------------------------------------------------------------------
extern "C" void kernel_launch(void* const* d_in, const int* in_sizes, int n_in,
                              void* d_out, int out_size) {
    const float4*    x4   = (const float4*)d_in[0];
    const long long* ei   = (const long long*)d_in[1];
    const float4*    W4   = (const float4*)d_in[2];
    const float*     bias = (const float*)d_in[3];
    float4*          out4 = (float4*)d_out;

    const int smem_bytes = 8192 * 16 + 64 * 65 * 16;  // 131072 + 66560 = 197632
    cudaFuncSetAttribute(gemm_norm_kernel,
                         cudaFuncAttributeMaxDynamicSharedMemorySize, smem_bytes);

    const int EB = (N_EDGES + 255) / 256;   // 3125

    k_zero<<<SCAN_BLOCKS, 256>>>(ei);
    k_hist<<<EB, 256>>>(ei);
    k_scan<<<SCAN_BLOCKS, 256>>>();
    k_binfill<<<EB, 256>>>(ei);
    k_aggregate<<<(N_NODES * 32 + 255) / 256, 256>>>(x4);
    gemm_norm_kernel<<<GEMM_GRID, 256, smem_bytes>>>(x4, W4, bias, out4);
}

// round 9
// speedup vs baseline: 1.9066x; 1.1912x over previous
#include <cuda_runtime.h>
#include <cuda_bf16.h>
#include <cstdint>

#define N_NODES 50000
#define N_EDGES 800000
#define SCAN_BLOCKS ((N_NODES + 255) / 256)   // 196
#define GEMM_ROWS 128
#define NTILES ((N_NODES + GEMM_ROWS - 1) / GEMM_ROWS)   // 391
#define GEMM_GRID 148

// ---- scratch (device globals; no allocs) ----
__device__ __align__(16) float4 g_neigh4[N_NODES * 32];   // mean-aggregated neigh
__device__ int g_deg_i[N_NODES];
__device__ int g_cursor[N_NODES];
__device__ int g_src_bin[N_EDGES];
__device__ int g_scan_val[SCAN_BLOCKS];
__device__ volatile int g_scan_flag[SCAN_BLOCKS];
__device__ int g_ei_is64;

// ---- helpers: dtype-agnostic edge index reads ----
__device__ __forceinline__ int load_src(const long long* ei, int e) {
    return g_ei_is64 ? (int)__ldg(ei + e) : __ldg(((const int*)ei) + e);
}
__device__ __forceinline__ int load_dst(const long long* ei, int e) {
    return g_ei_is64 ? (int)__ldg(ei + N_EDGES + e) : __ldg(((const int*)ei) + N_EDGES + e);
}

// ===========================================================================
// Edge pipeline (unchanged — passing, near floor)
// ===========================================================================
__global__ void __launch_bounds__(256) k_zero(const long long* __restrict__ ei) {
    int i = blockIdx.x * blockDim.x + threadIdx.x;
    if (i < N_NODES) g_deg_i[i] = 0;
    if (i < SCAN_BLOCKS) g_scan_flag[i] = 0;
    if (i == 0) {
        int ok = 1;
        for (int k = 0; k < 64; k++) {
            long long v = ei[k];
            if (v < 0 || v >= N_NODES) { ok = 0; break; }
        }
        g_ei_is64 = ok;
    }
}

__global__ void __launch_bounds__(256) k_hist(const long long* __restrict__ ei) {
    int e = blockIdx.x * blockDim.x + threadIdx.x;
    if (e >= N_EDGES) return;
    int d = load_dst(ei, e);
    if ((unsigned)d < N_NODES) atomicAdd(&g_deg_i[d], 1);
}

__global__ void __launch_bounds__(256) k_scan() {
    __shared__ int s[256];
    __shared__ int carry;
    const int b = blockIdx.x;
    const int tid = threadIdx.x;
    const int i = b * 256 + tid;

    int v = (i < N_NODES) ? g_deg_i[i] : 0;
    s[tid] = v;
    __syncthreads();
    int acc = v;
    #pragma unroll
    for (int off = 1; off < 256; off <<= 1) {
        int t = (tid >= off) ? s[tid - off] : 0;
        __syncthreads();
        acc += t;
        s[tid] = acc;
        __syncthreads();
    }
    if (tid == 255) {
        g_scan_val[b] = acc;
        __threadfence();
        g_scan_flag[b] = 1;
    }
    if (tid == 0) carry = 0;
    __syncthreads();

    int sum = 0;
    for (int p = tid; p < b; p += 256) {
        while (g_scan_flag[p] == 0) { }
        sum += g_scan_val[p];
    }
    if (sum) atomicAdd(&carry, sum);
    __syncthreads();

    if (i < N_NODES) g_cursor[i] = carry + (acc - v);
}

__global__ void __launch_bounds__(256) k_binfill(const long long* __restrict__ ei) {
    int e = blockIdx.x * blockDim.x + threadIdx.x;
    if (e >= N_EDGES) return;
    int s = load_src(ei, e);
    int d = load_dst(ei, e);
    if ((unsigned)s >= N_NODES || (unsigned)d >= N_NODES) return;
    int pos = atomicAdd(&g_cursor[d], 1);
    g_src_bin[pos] = s;
}

__global__ void __launch_bounds__(256) k_aggregate(const float4* __restrict__ x4) {
    int n = (blockIdx.x * blockDim.x + threadIdx.x) >> 5;
    int lane = threadIdx.x & 31;
    if (n >= N_NODES) return;

    int end = g_cursor[n];
    int deg = g_deg_i[n];
    int beg = end - deg;

    float4 a0 = make_float4(0.f, 0.f, 0.f, 0.f);
    float4 a1 = make_float4(0.f, 0.f, 0.f, 0.f);

    for (int base = beg; base < end; base += 32) {
        int m = min(32, end - base);
        int s = (base + lane < end) ? __ldg(g_src_bin + base + lane) : 0;
        int j = 0;
        for (; j + 1 < m; j += 2) {
            int s0 = __shfl_sync(0xffffffffu, s, j);
            int s1 = __shfl_sync(0xffffffffu, s, j + 1);
            float4 v0 = __ldg(x4 + s0 * 32 + lane);
            float4 v1 = __ldg(x4 + s1 * 32 + lane);
            a0.x += v0.x; a0.y += v0.y; a0.z += v0.z; a0.w += v0.w;
            a1.x += v1.x; a1.y += v1.y; a1.z += v1.z; a1.w += v1.w;
        }
        if (j < m) {
            int s0 = __shfl_sync(0xffffffffu, s, j);
            float4 v0 = __ldg(x4 + s0 * 32 + lane);
            a0.x += v0.x; a0.y += v0.y; a0.z += v0.z; a0.w += v0.w;
        }
    }
    float sc = 1.0f / fmaxf((float)deg, 1.0f);
    g_neigh4[n * 32 + lane] = make_float4((a0.x + a1.x) * sc, (a0.y + a1.y) * sc,
                                          (a0.z + a1.z) * sc, (a0.w + a1.w) * sc);
}

// ===========================================================================
// K6: mma.sync bf16-split GEMM + bias + row L2-normalize (persistent).
// D = A_hi B_hi^T + A_hi B_lo^T + A_lo B_hi^T  (fp32 accum in registers)
// Tile 128x128, 8 warps ALONG M ONLY: warp w owns rows w*16..+15 and ALL
// 128 columns (16 n-tiles) -> the row L2-norm reduction is fully intra-warp
// (lanes sharing l>>2). [R8 bug: rows were split across 2 warps -> partial
// norms -> rel_err 0.42.]
// SMEM tiles: [rows][256 bf16], row stride 528 B. Plain (non-trans)
// ldmatrix matches both a-frag and b-frag since A and W are k-contiguous.
// ===========================================================================
#define GSTRIDE 528
#define SM_BIAS 0
#define SM_A    1024
#define SM_BHI  (SM_A   + 128 * GSTRIDE)
#define SM_BLO  (SM_BHI + 128 * GSTRIDE)
#define SM_TOT  (SM_BLO + 128 * GSTRIDE)   // 203776 B

__device__ __forceinline__ uint32_t smem_u32(const void* p) {
    uint32_t a;
    asm("{ .reg .u64 t; cvta.to.shared.u64 t, %1; cvt.u32.u64 %0, t; }" : "=r"(a) : "l"(p));
    return a;
}

__device__ __forceinline__ void ldsm_x4(uint32_t& r0, uint32_t& r1, uint32_t& r2,
                                        uint32_t& r3, uint32_t addr) {
    asm volatile("ldmatrix.sync.aligned.m8n8.x4.shared.b16 {%0,%1,%2,%3}, [%4];"
                 : "=r"(r0), "=r"(r1), "=r"(r2), "=r"(r3) : "r"(addr));
}

__device__ __forceinline__ void mma_bf16(float* c, const uint32_t* a, const uint32_t* b) {
    asm volatile(
        "mma.sync.aligned.m16n8k16.row.col.f32.bf16.bf16.f32 "
        "{%0,%1,%2,%3}, {%4,%5,%6,%7}, {%8,%9}, {%0,%1,%2,%3};"
        : "+f"(c[0]), "+f"(c[1]), "+f"(c[2]), "+f"(c[3])
        : "r"(a[0]), "r"(a[1]), "r"(a[2]), "r"(a[3]), "r"(b[0]), "r"(b[1]));
}

__device__ __forceinline__ uint2 cvt_hi4(float4 v) {
    __nv_bfloat162 a = __floats2bfloat162_rn(v.x, v.y);
    __nv_bfloat162 b = __floats2bfloat162_rn(v.z, v.w);
    uint2 r;
    r.x = *reinterpret_cast<uint32_t*>(&a);
    r.y = *reinterpret_cast<uint32_t*>(&b);
    return r;
}
__device__ __forceinline__ uint2 cvt_lo4(float4 v) {
    __nv_bfloat162 a = __floats2bfloat162_rn(v.x, v.y);
    __nv_bfloat162 b = __floats2bfloat162_rn(v.z, v.w);
    float4 l = make_float4(v.x - __bfloat162float(a.x), v.y - __bfloat162float(a.y),
                           v.z - __bfloat162float(b.x), v.w - __bfloat162float(b.y));
    __nv_bfloat162 c = __floats2bfloat162_rn(l.x, l.y);
    __nv_bfloat162 d = __floats2bfloat162_rn(l.z, l.w);
    uint2 r;
    r.x = *reinterpret_cast<uint32_t*>(&c);
    r.y = *reinterpret_cast<uint32_t*>(&d);
    return r;
}

// one bf16 pass: C += A_warp_tile(16xK) @ B_tile(128xK)^T  -> 16x128
__device__ __forceinline__ void run_pass(uint32_t aA, const uint32_t* bA,
                                         float (*c)[4]) {
    #pragma unroll 4
    for (int k = 0; k < 16; k++) {
        uint32_t a[4], b[16][2];
        ldsm_x4(a[0], a[1], a[2], a[3], aA + k * 32);
        #pragma unroll
        for (int p = 0; p < 8; p++)
            ldsm_x4(b[2*p][0], b[2*p][1], b[2*p+1][0], b[2*p+1][1], bA[p] + k * 32);
        #pragma unroll
        for (int nt = 0; nt < 16; nt++)
            mma_bf16(c[nt], a, b[nt]);
    }
}

__global__ void __launch_bounds__(256, 1) gemm_norm_kernel(
    const float4* __restrict__ x4,
    const float4* __restrict__ W4,     // [128][64] float4 (W[c][k])
    const float*  __restrict__ bias,   // [128]
    float4*       __restrict__ out4)   // [N_NODES][32]
{
    extern __shared__ char smem[];
    const uint32_t sb = smem_u32(smem);
    const int tid  = threadIdx.x;
    const int lane = tid & 31;
    const int wid  = tid >> 5;      // warp w -> rows w*16..+15, all 128 cols

    // Stage W -> B_hi/B_lo (once per block); padded-stride layout
    for (int i = tid; i < 8192; i += 256) {
        int c = i >> 6, k4 = i & 63;
        float4 v = __ldg(W4 + i);
        uint32_t off = (uint32_t)(c * GSTRIDE + k4 * 8);
        *reinterpret_cast<uint2*>(smem + SM_BHI + off) = cvt_hi4(v);
        *reinterpret_cast<uint2*>(smem + SM_BLO + off) = cvt_lo4(v);
    }
    if (tid < 128) ((float*)(smem + SM_BIAS))[tid] = __ldg(bias + tid);
    __syncthreads();

    // Per-thread ldmatrix address offsets (constant across tiles/k)
    const int q = lane >> 3, r = lane & 7;
    // A x4: matrices = (rows0-7,k0-7)(rows8-15,k0-7)(rows0-7,k8-15)(rows8-15,k8-15)
    const uint32_t aRel = (uint32_t)((wid * 16 + (q & 1) * 8 + r) * GSTRIDE + (q >> 1) * 16);
    // B x4 per pair p (nt=2p,2p+1): (n0-7,k0-7)(n0-7,k8-15)(n8-15,k0-7)(n8-15,k8-15)
    uint32_t bRel[8];
    #pragma unroll
    for (int p = 0; p < 8; p++)
        bRel[p] = (uint32_t)((p * 16 + (q >> 1) * 8 + r) * GSTRIDE + (q & 1) * 16);

    float2* out2 = (float2*)out4;
    const float* bs = (const float*)(smem + SM_BIAS);

    for (int tile = blockIdx.x; tile < NTILES; tile += GEMM_GRID) {
        const int base = tile * GEMM_ROWS;

        // ---- stage A_hi ----
        for (int i = tid; i < 8192; i += 256) {
            int rr = i >> 6, k4 = i & 63;
            int row = base + rr;
            float4 v = make_float4(0.f, 0.f, 0.f, 0.f);
            if (row < N_NODES)
                v = (k4 < 32) ? __ldg(x4 + row * 32 + k4)
                              : g_neigh4[row * 32 + (k4 - 32)];
            *reinterpret_cast<uint2*>(smem + SM_A + rr * GSTRIDE + k4 * 8) = cvt_hi4(v);
        }
        __syncthreads();

        float c[16][4];
        #pragma unroll
        for (int nt = 0; nt < 16; nt++)
            #pragma unroll
            for (int j = 0; j < 4; j++) c[nt][j] = 0.f;

        uint32_t bHi[8], bLo[8];
        #pragma unroll
        for (int p = 0; p < 8; p++) {
            bHi[p] = sb + SM_BHI + bRel[p];
            bLo[p] = sb + SM_BLO + bRel[p];
        }

        // passes 1+2: A_hi*B_hi, A_hi*B_lo
        run_pass(sb + SM_A + aRel, bHi, c);
        run_pass(sb + SM_A + aRel, bLo, c);
        __syncthreads();   // all warps done reading A_hi

        // ---- restage A_lo ----
        for (int i = tid; i < 8192; i += 256) {
            int rr = i >> 6, k4 = i & 63;
            int row = base + rr;
            float4 v = make_float4(0.f, 0.f, 0.f, 0.f);
            if (row < N_NODES)
                v = (k4 < 32) ? __ldg(x4 + row * 32 + k4)
                              : g_neigh4[row * 32 + (k4 - 32)];
            *reinterpret_cast<uint2*>(smem + SM_A + rr * GSTRIDE + k4 * 8) = cvt_lo4(v);
        }
        __syncthreads();

        // pass 3: A_lo*B_hi
        run_pass(sb + SM_A + aRel, bHi, c);

        // ---- epilogue: bias, row L2-norm (full 128 cols in-warp), store ----
        // c[nt] = {c0,c1: row l>>2, cols nt*8+(l&3)*2+{0,1}; c2,c3: row l>>2+8}
        #pragma unroll
        for (int h = 0; h < 2; h++) {
            float o0[16], o1[16];
            float ss = 0.f;
            #pragma unroll
            for (int nt = 0; nt < 16; nt++) {
                int col = nt * 8 + (lane & 3) * 2;
                float v0 = c[nt][2*h + 0] + bs[col + 0];
                float v1 = c[nt][2*h + 1] + bs[col + 1];
                o0[nt] = v0; o1[nt] = v1;
                ss += v0 * v0 + v1 * v1;
            }
            // row owned by 4 lanes differing in lane&3
            ss += __shfl_xor_sync(0xffffffffu, ss, 1);
            ss += __shfl_xor_sync(0xffffffffu, ss, 2);
            float sc = 1.0f / fmaxf(sqrtf(ss), 1e-12f);

            int row = base + wid * 16 + h * 8 + (lane >> 2);
            if (row < N_NODES) {
                #pragma unroll
                for (int nt = 0; nt < 16; nt++)
                    out2[row * 64 + nt * 4 + (lane & 3)] =
                        make_float2(o0[nt] * sc, o1[nt] * sc);
            }
        }
        __syncthreads();   // A reused next tile
    }
}

// ---------------------------------------------------------------------------
extern "C" void kernel_launch(void* const* d_in, const int* in_sizes, int n_in,
                              void* d_out, int out_size) {
    const float4*    x4   = (const float4*)d_in[0];
    const long long* ei   = (const long long*)d_in[1];
    const float4*    W4   = (const float4*)d_in[2];
    const float*     bias = (const float*)d_in[3];
    float4*          out4 = (float4*)d_out;

    cudaFuncSetAttribute(gemm_norm_kernel,
                         cudaFuncAttributeMaxDynamicSharedMemorySize, SM_TOT);

    const int EB = (N_EDGES + 255) / 256;   // 3125

    k_zero<<<SCAN_BLOCKS, 256>>>(ei);
    k_hist<<<EB, 256>>>(ei);
    k_scan<<<SCAN_BLOCKS, 256>>>();
    k_binfill<<<EB, 256>>>(ei);
    k_aggregate<<<(N_NODES * 32 + 255) / 256, 256>>>(x4);
    gemm_norm_kernel<<<GEMM_GRID, 256, SM_TOT>>>(x4, W4, bias, out4);
}